// round 9
// baseline (speedup 1.0000x reference)
#include <cuda_runtime.h>
#include <cuda_bf16.h>
#include <math.h>
#include <stdint.h>

// ---------------- static problem constants ----------------
#define BB   2
#define SS   4096
#define HID  2048
#define NH   32
#define HD   64
#define MTOT (BB*SS)       // 8192
#define WDIM 64
#define TILE_TOK 128
#define QSCALE (0.125f * 1.4426950408889634f)   // ATT_SCALE * log2(e)
#define GK   2048          // GEMM K
#define BKC  32            // K chunk (floats)
#define NCHUNK (GK/BKC)    // 64
// smem layout per stage: A tile 128 rows x 36-float pitch; B tile 32 rows x 136-float pitch
#define A_PITCH 144        // bytes = 36 floats (bank: 4r+c distinct per frag load)
#define B_PITCH 544        // bytes = 136 floats (bank: 8k+n distinct per frag load)
#define A_TILE  (128*A_PITCH)   // 18432
#define B_TILE  (32*B_PITCH)    // 17408
#define STAGE_BYTES (A_TILE + B_TILE)  // 35840
#define NSTAGE 3
#define SMEM_GEMM (NSTAGE*STAGE_BYTES) // 107520

// ---------------- scratch ----------------
__device__ __align__(16) float g_q[(size_t)MTOT * HID];
__device__ __align__(16) float g_k[(size_t)MTOT * HID];
__device__ __align__(16) float g_v[(size_t)MTOT * HID];
__device__ __align__(16) float g_o[(size_t)MTOT * HID];

// ---------------- baseline-PTX helpers (harness targets sm_103: no tcgen05) ----
__device__ __forceinline__ uint32_t smem_u32(const void* p) {
    uint32_t a;
    asm("{ .reg .u64 t; cvta.to.shared.u64 t, %1; cvt.u32.u64 %0, t; }" : "=r"(a) : "l"(p));
    return a;
}
__device__ __forceinline__ void cp_async16(uint32_t dst, const void* src) {
    asm volatile("cp.async.ca.shared.global [%0], [%1], 16;" :: "r"(dst), "l"(src));
}
#define CP_COMMIT() asm volatile("cp.async.commit_group;" ::: "memory")
#define CP_WAIT1()  asm volatile("cp.async.wait_group 1;" ::: "memory")
#define CP_WAIT0()  asm volatile("cp.async.wait_group 0;" ::: "memory")
// round f32 -> tf32 (RN) in a 32-bit reg; unbiased 2^-11 operand error
__device__ __forceinline__ uint32_t to_tf32(float f) {
    uint32_t u;
    asm("cvt.rna.tf32.f32 %0, %1;" : "=r"(u) : "f"(f));
    return u;
}
__device__ __forceinline__ void mma_tf32(float* d, const uint32_t* a, const uint32_t* b) {
    asm volatile("mma.sync.aligned.m16n8k8.row.col.f32.tf32.tf32.f32 "
                 "{%0,%1,%2,%3}, {%4,%5,%6,%7}, {%8,%9}, {%0,%1,%2,%3};"
                 : "+f"(d[0]), "+f"(d[1]), "+f"(d[2]), "+f"(d[3])
                 : "r"(a[0]), "r"(a[1]), "r"(a[2]), "r"(a[3]), "r"(b[0]), "r"(b[1]));
}

// ---------------- tf32 single-pass GEMM: C[M-blk,N-blk] = A[M,K] @ B[K,N] ----------------
// A f32 row-major (raw activations), B f32 row-major [K,N] (raw weights, NO transpose).
// CTA 128x128, 256 thr, 8 warps (2m x 4n), warp tile 64x32, K chunk 32, 3-stage cp.async.
// Fragment loads are scalar LDS.32 from pitched smem (conflict-free, no ldmatrix needed).
__device__ __forceinline__ void gemm_tf32(const float* __restrict__ A,
                                          const float* __restrict__ B,
                                          float* __restrict__ C,
                                          int m0, int n0, int ldc)
{
    extern __shared__ char smem[];
    const uint32_t sb = smem_u32(smem);
    const int t = threadIdx.x, wid = t >> 5, lane = t & 31;
    const int warp_m = wid & 1, warp_n = wid >> 1;
    const int lg = lane >> 2;   // group id 0..7
    const int lt = lane & 3;    // thread-in-group 0..3

    float acc[4][4][4];
    #pragma unroll
    for (int mi = 0; mi < 4; mi++)
        #pragma unroll
        for (int nj = 0; nj < 4; nj++)
            #pragma unroll
            for (int r = 0; r < 4; r++) acc[mi][nj][r] = 0.f;

    const float* asrc = A + (size_t)m0 * GK;

    // stage chunk c into slot c % NSTAGE: threads 0-127 load A, 128-255 load B
    auto stage = [&](int c) {
        uint32_t base = sb + (c % NSTAGE) * STAGE_BYTES;
        if (t < 128) {
            const float* src = asrc + (size_t)t * GK + c * BKC;
            uint32_t dst = base + (uint32_t)t * A_PITCH;
            #pragma unroll
            for (int i = 0; i < 8; i++)
                cp_async16(dst + i * 16, src + i * 4);
        } else {
            int j = t - 128, k = j >> 2, p = j & 3;
            const float* src = B + (size_t)(c * BKC + k) * HID + n0 + p * 32;
            uint32_t dst = base + A_TILE + (uint32_t)k * B_PITCH + p * 128;
            #pragma unroll
            for (int i = 0; i < 8; i++)
                cp_async16(dst + i * 16, src + i * 4);
        }
        CP_COMMIT();
    };

    stage(0);
    stage(1);
    CP_WAIT1();
    __syncthreads();

    for (int c = 0; c < NCHUNK; c++) {
        const uint32_t base = sb + (c % NSTAGE) * STAGE_BYTES;
        #pragma unroll
        for (int ks = 0; ks < 4; ks++) {          // 4 x k8 per chunk
            uint32_t af[4][4], bf[4][2];
            // A fragments: a0=(r+lg, k+lt) a1=(+8 row) a2=(+4 col) a3=(both)
            #pragma unroll
            for (int mi = 0; mi < 4; mi++) {
                uint32_t r0 = base + (uint32_t)(warp_m * 64 + mi * 16 + lg) * A_PITCH
                            + (ks * 8 + lt) * 4;
                af[mi][0] = to_tf32(*(const float*)(smem + (r0 - sb)));
                af[mi][1] = to_tf32(*(const float*)(smem + (r0 - sb) + 8 * A_PITCH));
                af[mi][2] = to_tf32(*(const float*)(smem + (r0 - sb) + 16));
                af[mi][3] = to_tf32(*(const float*)(smem + (r0 - sb) + 8 * A_PITCH + 16));
            }
            // B fragments from [K,N] tile: b0=(k+lt, n+lg), b1=(k+lt+4, n+lg)
            #pragma unroll
            for (int nj = 0; nj < 4; nj++) {
                uint32_t b0 = (base - sb) + A_TILE + (uint32_t)(ks * 8 + lt) * B_PITCH
                            + (warp_n * 32 + nj * 8 + lg) * 4;
                bf[nj][0] = to_tf32(*(const float*)(smem + b0));
                bf[nj][1] = to_tf32(*(const float*)(smem + b0 + 4 * B_PITCH));
            }
            #pragma unroll
            for (int mi = 0; mi < 4; mi++)
                #pragma unroll
                for (int nj = 0; nj < 4; nj++)
                    mma_tf32(acc[mi][nj], af[mi], bf[nj]);
        }
        // stage chunk c+2 into slot (c+2)%3 (untouched this iteration); barrier
        // publishes chunk c+1 and protects slot c%3 from stage(c+3).
        if (c + 2 < NCHUNK) {
            stage(c + 2);
            CP_WAIT1();
        } else {
            CP_WAIT0();
        }
        __syncthreads();
    }

    // epilogue: c0,c1=(row=lg, col=2*lt+{0,1}), c2,c3=(row+8)
    #pragma unroll
    for (int mi = 0; mi < 4; mi++) {
        int row = m0 + warp_m * 64 + mi * 16 + lg;
        #pragma unroll
        for (int nj = 0; nj < 4; nj++) {
            int col = n0 + warp_n * 32 + nj * 8 + lt * 2;
            *(float2*)(C + (size_t)row * ldc + col) =
                make_float2(acc[mi][nj][0], acc[mi][nj][1]);
            *(float2*)(C + (size_t)(row + 8) * ldc + col) =
                make_float2(acc[mi][nj][2], acc[mi][nj][3]);
        }
    }
}

__global__ __launch_bounds__(256) void qkv_tf32(const float* __restrict__ hs,
                                               const float* __restrict__ Wq,
                                               const float* __restrict__ Wk,
                                               const float* __restrict__ Wv)
{
    const int which = blockIdx.x >> 4;
    const int n0 = (blockIdx.x & 15) * 128, m0 = blockIdx.y * 128;
    const float* B = (which == 0) ? Wq : (which == 1) ? Wk : Wv;
    float*       C = (which == 0) ? g_q : (which == 1) ? g_k : g_v;
    gemm_tf32(hs, B, C, m0, n0, HID);
}

__global__ __launch_bounds__(256) void out_tf32(const float* __restrict__ Wo,
                                                float* __restrict__ out)
{
    gemm_tf32(g_o, Wo, out, blockIdx.y * 128, blockIdx.x * 128, HID);
}

// ---------------- block-sparse sliding-tile attention (SIMT, exp2-domain) ----------------
__global__ __launch_bounds__(128) void attn_kernel(const float* __restrict__ Q,
                                                   const float* __restrict__ K,
                                                   const float* __restrict__ V,
                                                   float* __restrict__ O)
{
    extern __shared__ float4 att_smem[];
    float4* Ks = att_smem;
    float4* Vs = att_smem + TILE_TOK * 16;

    const int tt = blockIdx.x & 31;
    const int h = (blockIdx.x >> 5) & 31;
    const int b = blockIdx.x >> 10;

    const int tr = tt >> 2, tc = tt & 3;
    const int cr = min(max(tr, 1), 7);
    const int cc = min(max(tc, 1), 3);

    const int tid = threadIdx.x;
    const int th = tid >> 4, tw = tid & 15;
    const int qs = (tr * 8 + th) * WDIM + (tc * 16 + tw);

    const size_t base = ((size_t)b * SS) * HID + (size_t)h * HD;

    // q pre-scaled by ATT_SCALE*log2(e): scores land directly in log2 domain.
    float4 q[16];
    {
        const float* qp = Q + base + (size_t)qs * HID;
        #pragma unroll
        for (int d = 0; d < 16; d++) {
            float4 x = *(const float4*)(qp + d * 4);
            q[d] = make_float4(x.x * QSCALE, x.y * QSCALE, x.z * QSCALE, x.w * QSCALE);
        }
    }

    float m = -INFINITY, l = 0.f;
    float4 acc[16];
    #pragma unroll
    for (int d = 0; d < 16; d++) acc[d] = make_float4(0.f, 0.f, 0.f, 0.f);

    #pragma unroll 1
    for (int w = 0; w < 4; w++) {
        const int ktr = cr + (w >> 1) - 1;
        const int ktc = cc + (w & 1) - 1;

        __syncthreads();
        #pragma unroll
        for (int i = 0; i < 16; i++) {
            int tok = i * 8 + (tid >> 4);
            int comp = tid & 15;
            int s = (ktr * 8 + (tok >> 4)) * WDIM + (ktc * 16 + (tok & 15));
            size_t g = base + (size_t)s * HID + comp * 4;
            Ks[tok * 16 + comp] = *(const float4*)(K + g);
            Vs[tok * 16 + comp] = *(const float4*)(V + g);
        }
        __syncthreads();

        #pragma unroll 4
        for (int j = 0; j < TILE_TOK; j++) {
            float s = 0.f;
            #pragma unroll
            for (int d = 0; d < 16; d++) {
                float4 kk = Ks[j * 16 + d];
                s += q[d].x * kk.x + q[d].y * kk.y + q[d].z * kk.z + q[d].w * kk.w;
            }
            if (s > m) {                  // lazy rescale (rare after warmup)
                float f = exp2f(m - s);
                l *= f;
                #pragma unroll
                for (int d = 0; d < 16; d++) {
                    acc[d].x *= f; acc[d].y *= f; acc[d].z *= f; acc[d].w *= f;
                }
                m = s;
            }
            float p = exp2f(s - m);
            l += p;
            #pragma unroll
            for (int d = 0; d < 16; d++) {
                float4 vv = Vs[j * 16 + d];
                acc[d].x += p * vv.x; acc[d].y += p * vv.y;
                acc[d].z += p * vv.z; acc[d].w += p * vv.w;
            }
        }
    }

    const float inv_l = 1.f / l;
    __syncthreads();
    #pragma unroll
    for (int d = 0; d < 16; d++) {
        float4 a = acc[d];
        Ks[tid * 16 + d] = make_float4(a.x * inv_l, a.y * inv_l, a.z * inv_l, a.w * inv_l);
    }
    __syncthreads();
    #pragma unroll
    for (int i = 0; i < 16; i++) {
        int tok = i * 8 + (tid >> 4);
        int comp = tid & 15;
        int s = (tr * 8 + (tok >> 4)) * WDIM + (tc * 16 + (tok & 15));
        *(float4*)(O + base + (size_t)s * HID + comp * 4) = Ks[tok * 16 + comp];
    }
}

// ---------------- launch ----------------
extern "C" void kernel_launch(void* const* d_in, const int* in_sizes, int n_in,
                              void* d_out, int out_size)
{
    const float* hs = (const float*)d_in[0];
    const float* Wq = (const float*)d_in[1];
    const float* Wk = (const float*)d_in[2];
    const float* Wv = (const float*)d_in[3];
    const float* Wo = (const float*)d_in[4];
    float* out = (float*)d_out;

    float *q, *k, *v, *o;
    cudaGetSymbolAddress((void**)&q, g_q);
    cudaGetSymbolAddress((void**)&k, g_k);
    cudaGetSymbolAddress((void**)&v, g_v);
    cudaGetSymbolAddress((void**)&o, g_o);

    cudaFuncSetAttribute(attn_kernel, cudaFuncAttributeMaxDynamicSharedMemorySize, 65536);
    cudaFuncSetAttribute(qkv_tf32, cudaFuncAttributeMaxDynamicSharedMemorySize, SMEM_GEMM);
    cudaFuncSetAttribute(out_tf32, cudaFuncAttributeMaxDynamicSharedMemorySize, SMEM_GEMM);

    // 1. fused QKV projection — tf32 single-pass, weights consumed untransposed
    qkv_tf32<<<dim3(48, 64), 256, SMEM_GEMM>>>(hs, Wq, Wk, Wv);
    // 2. block-sparse attention (fp32 SIMT)
    attn_kernel<<<BB * NH * 32, 128, 65536>>>(q, k, v, o);
    // 3. output projection
    out_tf32<<<dim3(16, 64), 256, SMEM_GEMM>>>(Wo, out);
}

// round 14
// speedup vs baseline: 1.7003x; 1.7003x over previous
#include <cuda_runtime.h>
#include <cuda_bf16.h>
#include <math.h>
#include <stdint.h>

// ---------------- static problem constants ----------------
#define BB   2
#define SS   4096
#define HID  2048
#define NH   32
#define HD   64
#define MTOT (BB*SS)       // 8192
#define WDIM 64
#define TILE_TOK 128
#define QSCALE (0.125f * 1.4426950408889634f)   // ATT_SCALE * log2(e)
#define GK   2048          // GEMM K
#define BKC  32            // K chunk (floats)
#define NCHUNK (GK/BKC)    // 64
#define TILE_BYTES 16384   // 128 rows x 32 f32
#define STAGE_BYTES (2*TILE_BYTES)      // A + B
#define NSTAGE 3
#define SMEM_GEMM (NSTAGE*STAGE_BYTES)  // 98304

// ---------------- scratch ----------------
__device__ __align__(16) float g_q[(size_t)MTOT * HID];
__device__ __align__(16) float g_k[(size_t)MTOT * HID];
__device__ __align__(16) float g_v[(size_t)MTOT * HID];
__device__ __align__(16) float g_o[(size_t)MTOT * HID];
__device__ __align__(16) float g_wt[(size_t)4 * HID * HID];  // [w][N][K] tf32 bits
__device__ __align__(16) float g_a[(size_t)MTOT * HID];      // hs, tf32 bits

// ---------------- baseline-PTX helpers (harness targets sm_103: no tcgen05) ----
__device__ __forceinline__ uint32_t smem_u32(const void* p) {
    uint32_t a;
    asm("{ .reg .u64 t; cvta.to.shared.u64 t, %1; cvt.u32.u64 %0, t; }" : "=r"(a) : "l"(p));
    return a;
}
__device__ __forceinline__ void cp_async16(uint32_t dst, const void* src) {
    asm volatile("cp.async.ca.shared.global [%0], [%1], 16;" :: "r"(dst), "l"(src));
}
#define CP_COMMIT() asm volatile("cp.async.commit_group;" ::: "memory")
#define CP_WAIT1()  asm volatile("cp.async.wait_group 1;" ::: "memory")
#define CP_WAIT0()  asm volatile("cp.async.wait_group 0;" ::: "memory")
__device__ __forceinline__ float to_tf32_f(float f) {
    uint32_t u;
    asm("cvt.rna.tf32.f32 %0, %1;" : "=r"(u) : "f"(f));
    return __uint_as_float(u);
}
__device__ __forceinline__ void ldm_x4(uint32_t& r0, uint32_t& r1, uint32_t& r2,
                                       uint32_t& r3, uint32_t addr) {
    asm volatile("ldmatrix.sync.aligned.m8n8.x4.shared.b16 {%0,%1,%2,%3}, [%4];"
                 : "=r"(r0), "=r"(r1), "=r"(r2), "=r"(r3) : "r"(addr));
}
__device__ __forceinline__ void mma_tf32(float* d, const uint32_t* a, const uint32_t* b) {
    asm volatile("mma.sync.aligned.m16n8k8.row.col.f32.tf32.tf32.f32 "
                 "{%0,%1,%2,%3}, {%4,%5,%6,%7}, {%8,%9}, {%0,%1,%2,%3};"
                 : "+f"(d[0]), "+f"(d[1]), "+f"(d[2]), "+f"(d[3])
                 : "r"(a[0]), "r"(a[1]), "r"(a[2]), "r"(a[3]), "r"(b[0]), "r"(b[1]));
}

// ---------------- pre-pass: W[K,N] f32 -> g_wt[z][N,K] (tf32-rounded) ----------------
__global__ __launch_bounds__(256) void trans_w(const float* __restrict__ W0,
                                               const float* __restrict__ W1,
                                               const float* __restrict__ W2,
                                               const float* __restrict__ W3)
{
    __shared__ float s[64][65];
    const int z = blockIdx.z;
    const float* W = (z == 0) ? W0 : (z == 1) ? W1 : (z == 2) ? W2 : W3;
    float* Wt = g_wt + (size_t)z * HID * HID;
    const int k0 = blockIdx.y * 64, n0 = blockIdx.x * 64;
    const int t = threadIdx.x;
    #pragma unroll
    for (int i = 0; i < 16; i++) {
        int idx = t + i * 256, kl = idx >> 6, nl = idx & 63;
        s[kl][nl] = W[(size_t)(k0 + kl) * HID + n0 + nl];
    }
    __syncthreads();
    #pragma unroll
    for (int i = 0; i < 16; i++) {
        int idx = t + i * 256, nl = idx >> 6, kl = idx & 63;
        Wt[(size_t)(n0 + nl) * HID + k0 + kl] = to_tf32_f(s[kl][nl]);
    }
}

// ---------------- pre-pass: hs f32 -> g_a (tf32-rounded) ----------------
__global__ __launch_bounds__(256) void cvt_a(const float* __restrict__ A)
{
    size_t base = ((size_t)blockIdx.x * 256 + threadIdx.x) * 4;
    float4 x = *(const float4*)(A + base);
    x.x = to_tf32_f(x.x); x.y = to_tf32_f(x.y);
    x.z = to_tf32_f(x.z); x.w = to_tf32_f(x.w);
    *(float4*)(g_a + base) = x;
}

// ---------------- tf32 single-pass GEMM with ldmatrix fragments ----------------
// A [M,K] f32 (tf32 bits), B [N,K] f32 (tf32 bits), C f32.
// CTA 128x128, 256 thr, 8 warps (2m x 4n), warp tile 64x32, K chunk 32, 3-stage cp.async.
// smem tiles 128 rows x 32 f32, 16B-unit addr = row*8 + (colu ^ (row&7)).
__device__ __forceinline__ void gemm_tf32(const float* __restrict__ A,
                                          const float* __restrict__ B,
                                          float* __restrict__ C,
                                          int m0, int n0, int ldc)
{
    extern __shared__ char smem[];
    const uint32_t sb = smem_u32(smem);
    const int t = threadIdx.x, wid = t >> 5, lane = t & 31;
    const int warp_m = wid & 1, warp_n = wid >> 1;
    const int lg = lane >> 2, lt = lane & 3;

    float acc[4][4][4];
    #pragma unroll
    for (int mi = 0; mi < 4; mi++)
        #pragma unroll
        for (int nj = 0; nj < 4; nj++)
            #pragma unroll
            for (int r = 0; r < 4; r++) acc[mi][nj][r] = 0.f;

    const float* asrc = A + (size_t)m0 * GK;
    const float* bsrc = B + (size_t)n0 * GK;

    // stage chunk c into slot c%3: 256 thr x (4 A-units + 4 B-units) of 16B
    auto stage = [&](int c) {
        uint32_t base = sb + (c % NSTAGE) * STAGE_BYTES;
        const float* as = asrc + c * BKC;
        const float* bs = bsrc + c * BKC;
        #pragma unroll
        for (int i = 0; i < 4; i++) {
            int u = t + 256 * i, row = u >> 3, col = u & 7;
            uint32_t du = (uint32_t)(row * 8 + (col ^ (row & 7))) * 16;
            cp_async16(base + du, as + (size_t)row * GK + col * 4);
            cp_async16(base + TILE_BYTES + du, bs + (size_t)row * GK + col * 4);
        }
        CP_COMMIT();
    };

    stage(0);
    stage(1);
    CP_WAIT1();
    __syncthreads();

    // per-lane ldmatrix addressing: matrix = lane>>3, row-in-matrix = lane&7
    const int lrow8 = lane & 7;
    const int lhalf = (lane >> 3) & 1;   // +8 rows for matrices 1,3
    const int lcu   = lane >> 4;         // +1 col-unit for matrices 2,3

    for (int c = 0; c < NCHUNK; c++) {
        const uint32_t base = sb + (c % NSTAGE) * STAGE_BYTES;
        #pragma unroll
        for (int ks = 0; ks < 4; ks++) {           // 4 x k8 per chunk
            uint32_t af[4][4], bf[4][2];
            #pragma unroll
            for (int mi = 0; mi < 4; mi++) {
                int row = warp_m * 64 + mi * 16 + lhalf * 8 + lrow8;
                int cu  = ks * 2 + lcu;
                ldm_x4(af[mi][0], af[mi][1], af[mi][2], af[mi][3],
                       base + (uint32_t)(row * 8 + (cu ^ (row & 7))) * 16);
            }
            #pragma unroll
            for (int nj2 = 0; nj2 < 2; nj2++) {
                int row = warp_n * 32 + nj2 * 16 + lhalf * 8 + lrow8;
                int cu  = ks * 2 + lcu;
                uint32_t r0, r1, r2, r3;
                ldm_x4(r0, r1, r2, r3,
                       base + TILE_BYTES + (uint32_t)(row * 8 + (cu ^ (row & 7))) * 16);
                bf[nj2 * 2][0] = r0;     bf[nj2 * 2][1] = r2;
                bf[nj2 * 2 + 1][0] = r1; bf[nj2 * 2 + 1][1] = r3;
            }
            #pragma unroll
            for (int mi = 0; mi < 4; mi++)
                #pragma unroll
                for (int nj = 0; nj < 4; nj++)
                    mma_tf32(acc[mi][nj], af[mi], bf[nj]);
        }
        if (c + 2 < NCHUNK) {
            stage(c + 2);       // slot (c+2)%3 untouched this iteration
            CP_WAIT1();         // chunk c+1 resident
        } else {
            CP_WAIT0();
        }
        __syncthreads();        // publish c+1, protect slot c%3 from stage(c+3)
    }

    #pragma unroll
    for (int mi = 0; mi < 4; mi++) {
        int row = m0 + warp_m * 64 + mi * 16 + lg;
        #pragma unroll
        for (int nj = 0; nj < 4; nj++) {
            int col = n0 + warp_n * 32 + nj * 8 + lt * 2;
            *(float2*)(C + (size_t)row * ldc + col) =
                make_float2(acc[mi][nj][0], acc[mi][nj][1]);
            *(float2*)(C + (size_t)(row + 8) * ldc + col) =
                make_float2(acc[mi][nj][2], acc[mi][nj][3]);
        }
    }
}

__global__ __launch_bounds__(256, 2) void qkv_tf32()
{
    const int which = blockIdx.x >> 4;
    const int n0 = (blockIdx.x & 15) * 128, m0 = blockIdx.y * 128;
    const float* B = g_wt + (size_t)which * HID * HID;
    float*       C = (which == 0) ? g_q : (which == 1) ? g_k : g_v;
    gemm_tf32(g_a, B, C, m0, n0, HID);
}

__global__ __launch_bounds__(256, 2) void out_tf32(float* __restrict__ out)
{
    gemm_tf32(g_o, g_wt + (size_t)3 * HID * HID, out,
              blockIdx.y * 128, blockIdx.x * 128, HID);
}

// ---------------- block-sparse sliding-tile attention (SIMT, exp2-domain) ----------------
// Output stored tf32-rounded (feeds the tf32 out-projection with zero extra pass).
__global__ __launch_bounds__(128) void attn_kernel(const float* __restrict__ Q,
                                                   const float* __restrict__ K,
                                                   const float* __restrict__ V,
                                                   float* __restrict__ O)
{
    extern __shared__ float4 att_smem[];
    float4* Ks = att_smem;
    float4* Vs = att_smem + TILE_TOK * 16;

    const int tt = blockIdx.x & 31;
    const int h = (blockIdx.x >> 5) & 31;
    const int b = blockIdx.x >> 10;

    const int tr = tt >> 2, tc = tt & 3;
    const int cr = min(max(tr, 1), 7);
    const int cc = min(max(tc, 1), 3);

    const int tid = threadIdx.x;
    const int th = tid >> 4, tw = tid & 15;
    const int qs = (tr * 8 + th) * WDIM + (tc * 16 + tw);

    const size_t base = ((size_t)b * SS) * HID + (size_t)h * HD;

    float4 q[16];
    {
        const float* qp = Q + base + (size_t)qs * HID;
        #pragma unroll
        for (int d = 0; d < 16; d++) {
            float4 x = *(const float4*)(qp + d * 4);
            q[d] = make_float4(x.x * QSCALE, x.y * QSCALE, x.z * QSCALE, x.w * QSCALE);
        }
    }

    float m = -INFINITY, l = 0.f;
    float4 acc[16];
    #pragma unroll
    for (int d = 0; d < 16; d++) acc[d] = make_float4(0.f, 0.f, 0.f, 0.f);

    #pragma unroll 1
    for (int w = 0; w < 4; w++) {
        const int ktr = cr + (w >> 1) - 1;
        const int ktc = cc + (w & 1) - 1;

        __syncthreads();
        #pragma unroll
        for (int i = 0; i < 16; i++) {
            int tok = i * 8 + (tid >> 4);
            int comp = tid & 15;
            int s = (ktr * 8 + (tok >> 4)) * WDIM + (ktc * 16 + (tok & 15));
            size_t g = base + (size_t)s * HID + comp * 4;
            Ks[tok * 16 + comp] = *(const float4*)(K + g);
            Vs[tok * 16 + comp] = *(const float4*)(V + g);
        }
        __syncthreads();

        #pragma unroll 4
        for (int j = 0; j < TILE_TOK; j++) {
            float s = 0.f;
            #pragma unroll
            for (int d = 0; d < 16; d++) {
                float4 kk = Ks[j * 16 + d];
                s += q[d].x * kk.x + q[d].y * kk.y + q[d].z * kk.z + q[d].w * kk.w;
            }
            if (s > m) {
                float f = exp2f(m - s);
                l *= f;
                #pragma unroll
                for (int d = 0; d < 16; d++) {
                    acc[d].x *= f; acc[d].y *= f; acc[d].z *= f; acc[d].w *= f;
                }
                m = s;
            }
            float p = exp2f(s - m);
            l += p;
            #pragma unroll
            for (int d = 0; d < 16; d++) {
                float4 vv = Vs[j * 16 + d];
                acc[d].x += p * vv.x; acc[d].y += p * vv.y;
                acc[d].z += p * vv.z; acc[d].w += p * vv.w;
            }
        }
    }

    const float inv_l = 1.f / l;
    __syncthreads();
    #pragma unroll
    for (int d = 0; d < 16; d++) {
        float4 a = acc[d];
        Ks[tid * 16 + d] = make_float4(to_tf32_f(a.x * inv_l), to_tf32_f(a.y * inv_l),
                                       to_tf32_f(a.z * inv_l), to_tf32_f(a.w * inv_l));
    }
    __syncthreads();
    #pragma unroll
    for (int i = 0; i < 16; i++) {
        int tok = i * 8 + (tid >> 4);
        int comp = tid & 15;
        int s = (tr * 8 + (tok >> 4)) * WDIM + (tc * 16 + (tok & 15));
        *(float4*)(O + base + (size_t)s * HID + comp * 4) = Ks[tok * 16 + comp];
    }
}

// ---------------- launch ----------------
extern "C" void kernel_launch(void* const* d_in, const int* in_sizes, int n_in,
                              void* d_out, int out_size)
{
    const float* hs = (const float*)d_in[0];
    const float* Wq = (const float*)d_in[1];
    const float* Wk = (const float*)d_in[2];
    const float* Wv = (const float*)d_in[3];
    const float* Wo = (const float*)d_in[4];
    float* out = (float*)d_out;

    float *q, *k, *v, *o;
    cudaGetSymbolAddress((void**)&q, g_q);
    cudaGetSymbolAddress((void**)&k, g_k);
    cudaGetSymbolAddress((void**)&v, g_v);
    cudaGetSymbolAddress((void**)&o, g_o);

    cudaFuncSetAttribute(attn_kernel, cudaFuncAttributeMaxDynamicSharedMemorySize, 65536);
    cudaFuncSetAttribute(qkv_tf32, cudaFuncAttributeMaxDynamicSharedMemorySize, SMEM_GEMM);
    cudaFuncSetAttribute(out_tf32, cudaFuncAttributeMaxDynamicSharedMemorySize, SMEM_GEMM);

    // 1. weights: transpose + tf32-round -> [N,K]
    trans_w<<<dim3(32, 32, 4), 256>>>(Wq, Wk, Wv, Wo);
    // 2. activations: tf32-round
    cvt_a<<<(MTOT * (size_t)HID) / 1024, 256>>>(hs);
    // 3. fused QKV projection (tf32 mma + ldmatrix)
    qkv_tf32<<<dim3(48, 64), 256, SMEM_GEMM>>>();
    // 4. block-sparse attention (writes tf32-rounded O)
    attn_kernel<<<BB * NH * 32, 128, 65536>>>(q, k, v, o);
    // 5. output projection
    out_tf32<<<dim3(16, 64), 256, SMEM_GEMM>>>(out);
}